// round 5
// baseline (speedup 1.0000x reference)
#include <cuda_runtime.h>
#include <cuda_fp16.h>
#include <math.h>

constexpr int NA = 50000;
constexpr int NT = 25000;
constexpr int DIN = 32;
constexpr int H = 64;
constexpr int E_AA = 800000;
constexpr int E_AT = 400000;
constexpr int E_TA = 400000;

constexpr int OFF_AA   = 0;
constexpr int OFF_AT_S = NA;
constexpr int OFF_TA_D = 2 * NA;
constexpr int OFF_AT_D = 3 * NA;
constexpr int OFF_TA_S = 3 * NA + NT;
constexpr int NTOT = 3 * NA + 2 * NT;

// scratch
__device__ int    g_cnt[NTOT];
__device__ float  g_dis[NTOT];
__device__ __half g_h16_A[(size_t)(NA + NT) * H];   // rows [0,NA)=h_aa, [NA,NA+NT)=h_ta
__device__ __half g_h16_at[(size_t)NA * H];         // agent->target features
__device__ float4 g_acc_a[(size_t)NA * H / 4];
__device__ float4 g_acc_t[(size_t)NT * H / 4];
// CSR (built once per launch; valid for both layers)
__device__ int  g_rs_a[NA + 1];
__device__ int  g_rs_t[NT + 1];
__device__ int  g_cur_a[NA];
__device__ int  g_cur_t[NT];
__device__ int2 g_ent_a[E_AA + E_TA];               // {src_idx into g_h16_A, w as bits}
__device__ int2 g_ent_t[E_AT];                      // {src agent, w as bits}

__device__ __forceinline__ uint4 pack_half8(const float* a) {
    __half2 h0 = __floats2half2_rn(a[0], a[1]);
    __half2 h1 = __floats2half2_rn(a[2], a[3]);
    __half2 h2 = __floats2half2_rn(a[4], a[5]);
    __half2 h3 = __floats2half2_rn(a[6], a[7]);
    uint4 u;
    u.x = *(unsigned*)&h0; u.y = *(unsigned*)&h1;
    u.z = *(unsigned*)&h2; u.w = *(unsigned*)&h3;
    return u;
}

// ---------------------------------------------------------------------------
__global__ void zero_cnt_kernel() {
    int i = blockIdx.x * blockDim.x + threadIdx.x;
    if (i < NTOT) g_cnt[i] = 0;
}

__global__ void count_all_kernel(const int* __restrict__ dst_aa,
                                 const int* __restrict__ src_at,
                                 const int* __restrict__ dst_at,
                                 const int* __restrict__ src_ta,
                                 const int* __restrict__ dst_ta) {
    int i = blockIdx.x * blockDim.x + threadIdx.x;
    const int* p; int off, j;
    if (i < E_AA)                            { p = dst_aa; off = OFF_AA;   j = i; }
    else if (i < E_AA + E_AT)                { p = src_at; off = OFF_AT_S; j = i - E_AA; }
    else if (i < E_AA + 2 * E_AT)            { p = dst_at; off = OFF_AT_D; j = i - E_AA - E_AT; }
    else if (i < E_AA + 2 * E_AT + E_TA)     { p = src_ta; off = OFF_TA_S; j = i - E_AA - 2 * E_AT; }
    else if (i < E_AA + 2 * E_AT + 2 * E_TA) { p = dst_ta; off = OFF_TA_D; j = i - E_AA - 2 * E_AT - E_TA; }
    else return;
    atomicAdd(&g_cnt[off + p[j]], 1);
}

__global__ void dis_kernel() {
    int i = blockIdx.x * blockDim.x + threadIdx.x;
    if (i >= NTOT) return;
    int c = g_cnt[i];
    float d;
    if (i < NA) d = rsqrtf((float)c + 1.0f);
    else        d = (c > 0) ? rsqrtf((float)c) : 0.0f;
    g_dis[i] = d;
}

// One-block exclusive scan of (cnt1[i] + cnt2[i]) into row_start; zeroes cursor.
__global__ __launch_bounds__(1024) void scan_kernel(const int* __restrict__ cnt1,
                                                    const int* __restrict__ cnt2,
                                                    int n, int* __restrict__ row_start,
                                                    int* __restrict__ cursor) {
    __shared__ int part[1024];
    int tid = threadIdx.x;
    int chunk = (n + 1023) / 1024;
    int lo = min(tid * chunk, n), hi = min(lo + chunk, n);
    int s = 0;
    for (int i = lo; i < hi; i++) {
        int c = cnt1[i] + (cnt2 ? cnt2[i] : 0);
        s += c;
        cursor[i] = 0;
    }
    part[tid] = s;
    __syncthreads();
    // Hillis-Steele inclusive scan
    for (int off = 1; off < 1024; off <<= 1) {
        int v = part[tid];
        int u = (tid >= off) ? part[tid - off] : 0;
        __syncthreads();
        part[tid] = v + u;
        __syncthreads();
    }
    int pre = (tid == 0) ? 0 : part[tid - 1];
    for (int i = lo; i < hi; i++) {
        row_start[i] = pre;
        pre += cnt1[i] + (cnt2 ? cnt2[i] : 0);
    }
    if (tid == 1023) row_start[n] = part[1023];
}

// Place every edge into its dst segment (order within segment is arbitrary).
__global__ void fill_kernel(const int* __restrict__ src_aa, const int* __restrict__ dst_aa,
                            const int* __restrict__ src_ta, const int* __restrict__ dst_ta,
                            const int* __restrict__ src_at, const int* __restrict__ dst_at) {
    int i = blockIdx.x * blockDim.x + threadIdx.x;
    if (i < E_AA) {
        int s = src_aa[i], d = dst_aa[i];
        float w = g_dis[OFF_AA + s] * g_dis[OFF_AA + d];
        int pos = g_rs_a[d] + atomicAdd(&g_cur_a[d], 1);
        g_ent_a[pos] = make_int2(s, __float_as_int(w));
    } else if (i < E_AA + E_TA) {
        int j = i - E_AA;
        int s = src_ta[j], d = dst_ta[j];
        float w = g_dis[OFF_TA_S + s] * g_dis[OFF_TA_D + d];
        int pos = g_rs_a[d] + atomicAdd(&g_cur_a[d], 1);
        g_ent_a[pos] = make_int2(NA + s, __float_as_int(w));
    } else if (i < E_AA + E_TA + E_AT) {
        int j = i - E_AA - E_TA;
        int s = src_at[j], d = dst_at[j];
        float w = g_dis[OFF_AT_S + s] * g_dis[OFF_AT_D + d];
        int pos = g_rs_t[d] + atomicAdd(&g_cur_t[d], 1);
        g_ent_t[pos] = make_int2(s, __float_as_int(w));
    }
}

// Agent transform, fused epilogue (same as R4 but h_aa row goes into g_h16_A[0,NA)).
template <int K, bool RELU>
__global__ __launch_bounds__(256, 3) void transform_agent_kernel(
        const float4* __restrict__ x,
        const float* __restrict__ Wa, const float* __restrict__ Wb,
        const float* __restrict__ b_aa, const float* __restrict__ b_ta) {
    __shared__ float xs[64][K];
    __shared__ float Ws[K][128];
    __shared__ float bsum[64];
    int tid = threadIdx.x;
    int row0 = blockIdx.x * 64;
    for (int i = tid; i < K * 64; i += 256) {
        int k = i >> 6, c = i & 63;
        Ws[k][c]      = Wa[i];
        Ws[k][c + 64] = Wb[i];
    }
    if (tid < 64) bsum[tid] = b_aa[tid] + b_ta[tid];
    constexpr int KV = K / 4;
    for (int i = tid; i < 64 * KV; i += 256) {
        int r = i / KV, kv = i - r * KV;
        int row = row0 + r;
        float4 v = (row < NA) ? x[(size_t)row * KV + kv] : make_float4(0.f, 0.f, 0.f, 0.f);
        if (RELU) { v.x = fmaxf(v.x, 0.f); v.y = fmaxf(v.y, 0.f);
                    v.z = fmaxf(v.z, 0.f); v.w = fmaxf(v.w, 0.f); }
        *(float4*)&xs[r][kv * 4] = v;
    }
    __syncthreads();
    int ty = tid >> 4, tx = tid & 15;
    int r0 = ty * 4, c0 = tx * 8;
    float acc[4][8];
#pragma unroll
    for (int i = 0; i < 4; i++)
#pragma unroll
        for (int j = 0; j < 8; j++) acc[i][j] = 0.f;
#pragma unroll 4
    for (int k = 0; k < K; k++) {
        float w[8];
        *(float4*)&w[0] = *(float4*)&Ws[k][c0];
        *(float4*)&w[4] = *(float4*)&Ws[k][c0 + 4];
#pragma unroll
        for (int i = 0; i < 4; i++) {
            float xv = xs[r0 + i][k];
#pragma unroll
            for (int j = 0; j < 8; j++) acc[i][j] = fmaf(xv, w[j], acc[i][j]);
        }
    }
    bool is_a = (c0 < 64);
    int cc = is_a ? c0 : (c0 - 64);
#pragma unroll
    for (int i = 0; i < 4; i++) {
        int row = row0 + r0 + i;
        if (row >= NA) continue;
        uint4 hpk = pack_half8(&acc[i][0]);
        if (is_a) {
            *(uint4*)(g_h16_A + (size_t)row * H + cc) = hpk;
            float d = g_dis[OFF_AA + row];
            float dd = d * d;
            float4 o0, o1;
            o0.x = acc[i][0] * dd + bsum[cc + 0];
            o0.y = acc[i][1] * dd + bsum[cc + 1];
            o0.z = acc[i][2] * dd + bsum[cc + 2];
            o0.w = acc[i][3] * dd + bsum[cc + 3];
            o1.x = acc[i][4] * dd + bsum[cc + 4];
            o1.y = acc[i][5] * dd + bsum[cc + 5];
            o1.z = acc[i][6] * dd + bsum[cc + 6];
            o1.w = acc[i][7] * dd + bsum[cc + 7];
            g_acc_a[(size_t)row * (H / 4) + (cc >> 2)]     = o0;
            g_acc_a[(size_t)row * (H / 4) + (cc >> 2) + 1] = o1;
        } else {
            *(uint4*)(g_h16_at + (size_t)row * H + cc) = hpk;
        }
    }
}

// Target transform -> g_h16_A rows [NA, NA+NT)
template <int K, bool RELU>
__global__ __launch_bounds__(256, 3) void transform_target_kernel(
        const float4* __restrict__ x, const float* __restrict__ W) {
    __shared__ float xs[64][K];
    __shared__ float Ws[K][64];
    int tid = threadIdx.x;
    int row0 = blockIdx.x * 64;
    for (int i = tid; i < K * 64; i += 256) {
        int k = i >> 6, c = i & 63;
        Ws[k][c] = W[i];
    }
    constexpr int KV = K / 4;
    for (int i = tid; i < 64 * KV; i += 256) {
        int r = i / KV, kv = i - r * KV;
        int row = row0 + r;
        float4 v = (row < NT) ? x[(size_t)row * KV + kv] : make_float4(0.f, 0.f, 0.f, 0.f);
        if (RELU) { v.x = fmaxf(v.x, 0.f); v.y = fmaxf(v.y, 0.f);
                    v.z = fmaxf(v.z, 0.f); v.w = fmaxf(v.w, 0.f); }
        *(float4*)&xs[r][kv * 4] = v;
    }
    __syncthreads();
    int ty = tid >> 4, tx = tid & 15;
    int r0 = ty * 4, c0 = tx * 4;
    float acc[4][4];
#pragma unroll
    for (int i = 0; i < 4; i++)
#pragma unroll
        for (int j = 0; j < 4; j++) acc[i][j] = 0.f;
#pragma unroll 4
    for (int k = 0; k < K; k++) {
        float w[4];
        *(float4*)&w[0] = *(float4*)&Ws[k][c0];
#pragma unroll
        for (int i = 0; i < 4; i++) {
            float xv = xs[r0 + i][k];
#pragma unroll
            for (int j = 0; j < 4; j++) acc[i][j] = fmaf(xv, w[j], acc[i][j]);
        }
    }
#pragma unroll
    for (int i = 0; i < 4; i++) {
        int row = row0 + r0 + i;
        if (row >= NT) continue;
        __half2 h0 = __floats2half2_rn(acc[i][0], acc[i][1]);
        __half2 h1 = __floats2half2_rn(acc[i][2], acc[i][3]);
        uint2 u; u.x = *(unsigned*)&h0; u.y = *(unsigned*)&h1;
        *(uint2*)(g_h16_A + (size_t)(NA + row) * H + c0) = u;
    }
}

// Gather-based aggregation: warp per dst node, 2 edges in flight (16 lanes each).
// Agents add into pre-initialized g_acc_a; targets start from bias b_at.
__global__ __launch_bounds__(256) void agg_kernel(const float* __restrict__ b_at) {
    int gw = (blockIdx.x * 256 + threadIdx.x) >> 5;
    int lane = threadIdx.x & 31;
    int half = lane >> 4, sub = lane & 15;
    if (gw < NA) {
        int node = gw;
        int beg = g_rs_a[node], end = g_rs_a[node + 1];
        float ax = 0.f, ay = 0.f, az = 0.f, aw = 0.f;
        for (int p = beg + half; p < end; p += 2) {
            int2 ent = __ldg(&g_ent_a[p]);
            float w = __int_as_float(ent.y);
            uint2 raw = *(const uint2*)(g_h16_A + (size_t)ent.x * H + sub * 4);
            float2 f0 = __half22float2(*(__half2*)&raw.x);
            float2 f1 = __half22float2(*(__half2*)&raw.y);
            ax = fmaf(f0.x, w, ax); ay = fmaf(f0.y, w, ay);
            az = fmaf(f1.x, w, az); aw = fmaf(f1.y, w, aw);
        }
        ax += __shfl_down_sync(0xFFFFFFFFu, ax, 16);
        ay += __shfl_down_sync(0xFFFFFFFFu, ay, 16);
        az += __shfl_down_sync(0xFFFFFFFFu, az, 16);
        aw += __shfl_down_sync(0xFFFFFFFFu, aw, 16);
        if (half == 0) {
            float4 base = g_acc_a[(size_t)node * (H / 4) + sub];
            base.x += ax; base.y += ay; base.z += az; base.w += aw;
            g_acc_a[(size_t)node * (H / 4) + sub] = base;
        }
    } else if (gw < NA + NT) {
        int node = gw - NA;
        int beg = g_rs_t[node], end = g_rs_t[node + 1];
        float ax = 0.f, ay = 0.f, az = 0.f, aw = 0.f;
        for (int p = beg + half; p < end; p += 2) {
            int2 ent = __ldg(&g_ent_t[p]);
            float w = __int_as_float(ent.y);
            uint2 raw = *(const uint2*)(g_h16_at + (size_t)ent.x * H + sub * 4);
            float2 f0 = __half22float2(*(__half2*)&raw.x);
            float2 f1 = __half22float2(*(__half2*)&raw.y);
            ax = fmaf(f0.x, w, ax); ay = fmaf(f0.y, w, ay);
            az = fmaf(f1.x, w, az); aw = fmaf(f1.y, w, aw);
        }
        ax += __shfl_down_sync(0xFFFFFFFFu, ax, 16);
        ay += __shfl_down_sync(0xFFFFFFFFu, ay, 16);
        az += __shfl_down_sync(0xFFFFFFFFu, az, 16);
        aw += __shfl_down_sync(0xFFFFFFFFu, aw, 16);
        if (half == 0) {
            int c = sub * 4;
            float4 base = make_float4(b_at[c], b_at[c + 1], b_at[c + 2], b_at[c + 3]);
            base.x += ax; base.y += ay; base.z += az; base.w += aw;
            g_acc_t[(size_t)node * (H / 4) + sub] = base;
        }
    }
}

// One warp per row: out[row,:] = g[row,:] @ Wp + bp
__global__ void proj_kernel(const float* __restrict__ g,
                            const float* __restrict__ Wp,
                            const float* __restrict__ bp,
                            float* __restrict__ out, int n) {
    int idx = blockIdx.x * blockDim.x + threadIdx.x;
    int row = idx >> 5, lane = idx & 31;
    if (row >= n) return;
    float g0 = g[(size_t)row * H + lane];
    float g1 = g[(size_t)row * H + lane + 32];
    float p0 = g0 * Wp[lane * 2 + 0] + g1 * Wp[(lane + 32) * 2 + 0];
    float p1 = g0 * Wp[lane * 2 + 1] + g1 * Wp[(lane + 32) * 2 + 1];
#pragma unroll
    for (int o = 16; o; o >>= 1) {
        p0 += __shfl_down_sync(0xFFFFFFFFu, p0, o);
        p1 += __shfl_down_sync(0xFFFFFFFFu, p1, o);
    }
    if (lane == 0) {
        out[(size_t)row * 2 + 0] = p0 + bp[0];
        out[(size_t)row * 2 + 1] = p1 + bp[1];
    }
}

// ---------------------------------------------------------------------------
static inline int cdiv(long long a, int b) { return (int)((a + b - 1) / b); }

extern "C" void kernel_launch(void* const* d_in, const int* in_sizes, int n_in,
                              void* d_out, int out_size) {
    const float* x_agent  = (const float*)d_in[1];
    const float* x_target = (const float*)d_in[2];
    const int* src_aa = (const int*)d_in[3];
    const int* dst_aa = (const int*)d_in[4];
    const int* src_at = (const int*)d_in[5];
    const int* dst_at = (const int*)d_in[6];
    const int* src_ta = (const int*)d_in[7];
    const int* dst_ta = (const int*)d_in[8];
    const float* W1_aa = (const float*)d_in[9];
    const float* b1_aa = (const float*)d_in[10];
    const float* W1_at = (const float*)d_in[11];
    const float* b1_at = (const float*)d_in[12];
    const float* W1_ta = (const float*)d_in[13];
    const float* b1_ta = (const float*)d_in[14];
    const float* W2_aa = (const float*)d_in[15];
    const float* b2_aa = (const float*)d_in[16];
    const float* W2_at = (const float*)d_in[17];
    const float* b2_at = (const float*)d_in[18];
    const float* W2_ta = (const float*)d_in[19];
    const float* b2_ta = (const float*)d_in[20];
    const float* Wp_agent  = (const float*)d_in[21];
    const float* bp_agent  = (const float*)d_in[22];
    const float* Wp_target = (const float*)d_in[23];
    const float* bp_target = (const float*)d_in[24];
    float* out = (float*)d_out;

    void *p_acca, *p_acct, *p_cnt, *p_rsa, *p_rst, *p_cura, *p_curt;
    cudaGetSymbolAddress(&p_acca, g_acc_a);
    cudaGetSymbolAddress(&p_acct, g_acc_t);
    cudaGetSymbolAddress(&p_cnt,  g_cnt);
    cudaGetSymbolAddress(&p_rsa,  g_rs_a);
    cudaGetSymbolAddress(&p_rst,  g_rs_t);
    cudaGetSymbolAddress(&p_cura, g_cur_a);
    cudaGetSymbolAddress(&p_curt, g_cur_t);
    float* acc_a = (float*)p_acca;
    float* acc_t = (float*)p_acct;
    int* cnt   = (int*)p_cnt;
    int* rs_a  = (int*)p_rsa;
    int* rs_t  = (int*)p_rst;
    int* cur_a = (int*)p_cura;
    int* cur_t = (int*)p_curt;

    // ---- degrees / norms / CSR (once; reused by both layers) ----
    zero_cnt_kernel<<<cdiv(NTOT, 256), 256>>>();
    constexpr long long CNT_TOT = E_AA + 2LL * E_AT + 2LL * E_TA;
    count_all_kernel<<<cdiv(CNT_TOT, 256), 256>>>(dst_aa, src_at, dst_at, src_ta, dst_ta);
    dis_kernel<<<cdiv(NTOT, 256), 256>>>();
    scan_kernel<<<1, 1024>>>(cnt + OFF_AA,   cnt + OFF_TA_D, NA, rs_a, cur_a);
    scan_kernel<<<1, 1024>>>(cnt + OFF_AT_D, nullptr,        NT, rs_t, cur_t);
    constexpr long long E_TOT = E_AA + E_TA + E_AT;
    fill_kernel<<<cdiv(E_TOT, 256), 256>>>(src_aa, dst_aa, src_ta, dst_ta, src_at, dst_at);

    constexpr long long AGG_THREADS = (long long)(NA + NT) * 32;

    // ---- layer 1 ----
    transform_agent_kernel<DIN, false><<<cdiv(NA, 64), 256>>>(
        (const float4*)x_agent, W1_aa, W1_at, b1_aa, b1_ta);
    transform_target_kernel<DIN, false><<<cdiv(NT, 64), 256>>>(
        (const float4*)x_target, W1_ta);
    agg_kernel<<<cdiv(AGG_THREADS, 256), 256>>>(b1_at);

    // ---- layer 2 ----
    transform_agent_kernel<H, true><<<cdiv(NA, 64), 256>>>(
        (const float4*)acc_a, W2_aa, W2_at, b2_aa, b2_ta);
    transform_target_kernel<H, true><<<cdiv(NT, 64), 256>>>(
        (const float4*)acc_t, W2_ta);
    agg_kernel<<<cdiv(AGG_THREADS, 256), 256>>>(b2_at);

    // ---- output projections ----
    proj_kernel<<<cdiv((long long)NA * 32, 256), 256>>>(acc_a, Wp_agent,  bp_agent,  out, NA);
    proj_kernel<<<cdiv((long long)NT * 32, 256), 256>>>(acc_t, Wp_target, bp_target, out + (size_t)NA * 2, NT);
}

// round 6
// speedup vs baseline: 1.5998x; 1.5998x over previous
#include <cuda_runtime.h>
#include <cuda_fp16.h>
#include <math.h>

constexpr int NA = 50000;
constexpr int NT = 25000;
constexpr int DIN = 32;
constexpr int H = 64;
constexpr int E_AA = 800000;
constexpr int E_AT = 400000;
constexpr int E_TA = 400000;

constexpr int OFF_AA   = 0;
constexpr int OFF_AT_S = NA;
constexpr int OFF_TA_D = 2 * NA;
constexpr int OFF_AT_D = 3 * NA;
constexpr int OFF_TA_S = 3 * NA + NT;
constexpr int NTOT = 3 * NA + 2 * NT;

constexpr int NBLK_A = (NA + 1023) / 1024;   // 49
constexpr int NBLK_T = (NT + 1023) / 1024;   // 25
constexpr int NBLK   = NBLK_A + NBLK_T;      // 74

// scratch
__device__ int    g_cnt[NTOT];
__device__ float  g_dis[NTOT];
__device__ __half g_h16_A[(size_t)(NA + NT) * H];   // rows [0,NA)=h_aa, [NA,NA+NT)=h_ta
__device__ __half g_h16_at[(size_t)NA * H];         // agent->target features
__device__ float4 g_acc_a[(size_t)NA * H / 4];
__device__ float4 g_acc_t[(size_t)NT * H / 4];
// CSR (built once per launch; valid for both layers)
__device__ int  g_rs_a[NA + 1];
__device__ int  g_rs_t[NT + 1];
__device__ int  g_cur_a[NA];
__device__ int  g_cur_t[NT];
__device__ int2 g_ent_a[E_AA + E_TA];               // {src_idx into g_h16_A, w as bits}
__device__ int2 g_ent_t[E_AT];                      // {src agent, w as bits}
__device__ int  g_part[NBLK];
__device__ int  g_partscan[NBLK];

__device__ __forceinline__ uint4 pack_half8(const float* a) {
    __half2 h0 = __floats2half2_rn(a[0], a[1]);
    __half2 h1 = __floats2half2_rn(a[2], a[3]);
    __half2 h2 = __floats2half2_rn(a[4], a[5]);
    __half2 h3 = __floats2half2_rn(a[6], a[7]);
    uint4 u;
    u.x = *(unsigned*)&h0; u.y = *(unsigned*)&h1;
    u.z = *(unsigned*)&h2; u.w = *(unsigned*)&h3;
    return u;
}

// ---------------------------------------------------------------------------
__global__ void zero_cnt_kernel() {
    int i = blockIdx.x * blockDim.x + threadIdx.x;
    if (i < NTOT) g_cnt[i] = 0;
}

__global__ void count_all_kernel(const int* __restrict__ dst_aa,
                                 const int* __restrict__ src_at,
                                 const int* __restrict__ dst_at,
                                 const int* __restrict__ src_ta,
                                 const int* __restrict__ dst_ta) {
    int i = blockIdx.x * blockDim.x + threadIdx.x;
    const int* p; int off, j;
    if (i < E_AA)                            { p = dst_aa; off = OFF_AA;   j = i; }
    else if (i < E_AA + E_AT)                { p = src_at; off = OFF_AT_S; j = i - E_AA; }
    else if (i < E_AA + 2 * E_AT)            { p = dst_at; off = OFF_AT_D; j = i - E_AA - E_AT; }
    else if (i < E_AA + 2 * E_AT + E_TA)     { p = src_ta; off = OFF_TA_S; j = i - E_AA - 2 * E_AT; }
    else if (i < E_AA + 2 * E_AT + 2 * E_TA) { p = dst_ta; off = OFF_TA_D; j = i - E_AA - 2 * E_AT - E_TA; }
    else return;
    atomicAdd(&g_cnt[off + p[j]], 1);
}

__global__ void dis_kernel() {
    int i = blockIdx.x * blockDim.x + threadIdx.x;
    if (i >= NTOT) return;
    int c = g_cnt[i];
    float d;
    if (i < NA) d = rsqrtf((float)c + 1.0f);
    else        d = (c > 0) ? rsqrtf((float)c) : 0.0f;
    g_dis[i] = d;
}

// Phase 1: per-block local exclusive scan (1024 elems/block) + block partial.
// Blocks [0,NBLK_A) cover agent rows; [NBLK_A, NBLK) cover target rows.
__global__ __launch_bounds__(1024) void scan_local_kernel() {
    __shared__ int sm[1024];
    int b = blockIdx.x;
    bool isA = (b < NBLK_A);
    int base = isA ? b * 1024 : (b - NBLK_A) * 1024;
    int n = isA ? NA : NT;
    int tid = threadIdx.x;
    int i = base + tid;
    int v = 0;
    if (i < n) {
        if (isA) { v = g_cnt[OFF_AA + i] + g_cnt[OFF_TA_D + i]; g_cur_a[i] = 0; }
        else     { v = g_cnt[OFF_AT_D + i];                     g_cur_t[i] = 0; }
    }
    sm[tid] = v;
    __syncthreads();
#pragma unroll
    for (int off = 1; off < 1024; off <<= 1) {
        int u = (tid >= off) ? sm[tid - off] : 0;
        __syncthreads();
        sm[tid] += u;
        __syncthreads();
    }
    if (i < n) {
        int excl = sm[tid] - v;
        if (isA) g_rs_a[i] = excl; else g_rs_t[i] = excl;
    }
    if (tid == 1023) g_part[b] = sm[1023];
}

// Phase 2: segmented scan of the 74 block partials (one small block).
__global__ void scan_mid_kernel() {
    __shared__ int sp[NBLK];
    __shared__ int so[NBLK + 2];
    int tid = threadIdx.x;
    if (tid < NBLK) sp[tid] = g_part[tid];
    __syncthreads();
    if (tid == 0) {
        int s = 0;
        for (int b = 0; b < NBLK_A; b++) { so[b] = s; s += sp[b]; }
        so[NBLK] = s;        // total A
        s = 0;
        for (int b = NBLK_A; b < NBLK; b++) { so[b] = s; s += sp[b]; }
        so[NBLK + 1] = s;    // total T
    }
    __syncthreads();
    if (tid < NBLK) g_partscan[tid] = so[tid];
    if (tid == 0) { g_rs_a[NA] = so[NBLK]; g_rs_t[NT] = so[NBLK + 1]; }
}

// Phase 3: add block offsets.
__global__ __launch_bounds__(1024) void scan_add_kernel() {
    int b = blockIdx.x;
    if (b == 0) return;                    // block 0 of each segment has offset 0
    bool isA = (b < NBLK_A);
    if (!isA && b == NBLK_A) return;
    int base = isA ? b * 1024 : (b - NBLK_A) * 1024;
    int n = isA ? NA : NT;
    int i = base + threadIdx.x;
    int off = g_partscan[b];
    if (i < n) { if (isA) g_rs_a[i] += off; else g_rs_t[i] += off; }
}

// Place every edge into its dst segment (order within segment is arbitrary).
__global__ void fill_kernel(const int* __restrict__ src_aa, const int* __restrict__ dst_aa,
                            const int* __restrict__ src_ta, const int* __restrict__ dst_ta,
                            const int* __restrict__ src_at, const int* __restrict__ dst_at) {
    int i = blockIdx.x * blockDim.x + threadIdx.x;
    if (i < E_AA) {
        int s = src_aa[i], d = dst_aa[i];
        float w = g_dis[OFF_AA + s] * g_dis[OFF_AA + d];
        int pos = g_rs_a[d] + atomicAdd(&g_cur_a[d], 1);
        g_ent_a[pos] = make_int2(s, __float_as_int(w));
    } else if (i < E_AA + E_TA) {
        int j = i - E_AA;
        int s = src_ta[j], d = dst_ta[j];
        float w = g_dis[OFF_TA_S + s] * g_dis[OFF_TA_D + d];
        int pos = g_rs_a[d] + atomicAdd(&g_cur_a[d], 1);
        g_ent_a[pos] = make_int2(NA + s, __float_as_int(w));
    } else if (i < E_AA + E_TA + E_AT) {
        int j = i - E_AA - E_TA;
        int s = src_at[j], d = dst_at[j];
        float w = g_dis[OFF_AT_S + s] * g_dis[OFF_AT_D + d];
        int pos = g_rs_t[d] + atomicAdd(&g_cur_t[d], 1);
        g_ent_t[pos] = make_int2(s, __float_as_int(w));
    }
}

// Agent transform, fused epilogue.
template <int K, bool RELU>
__global__ __launch_bounds__(256, 3) void transform_agent_kernel(
        const float4* __restrict__ x,
        const float* __restrict__ Wa, const float* __restrict__ Wb,
        const float* __restrict__ b_aa, const float* __restrict__ b_ta) {
    __shared__ float xs[64][K];
    __shared__ float Ws[K][128];
    __shared__ float bsum[64];
    int tid = threadIdx.x;
    int row0 = blockIdx.x * 64;
    for (int i = tid; i < K * 64; i += 256) {
        int k = i >> 6, c = i & 63;
        Ws[k][c]      = Wa[i];
        Ws[k][c + 64] = Wb[i];
    }
    if (tid < 64) bsum[tid] = b_aa[tid] + b_ta[tid];
    constexpr int KV = K / 4;
    for (int i = tid; i < 64 * KV; i += 256) {
        int r = i / KV, kv = i - r * KV;
        int row = row0 + r;
        float4 v = (row < NA) ? x[(size_t)row * KV + kv] : make_float4(0.f, 0.f, 0.f, 0.f);
        if (RELU) { v.x = fmaxf(v.x, 0.f); v.y = fmaxf(v.y, 0.f);
                    v.z = fmaxf(v.z, 0.f); v.w = fmaxf(v.w, 0.f); }
        *(float4*)&xs[r][kv * 4] = v;
    }
    __syncthreads();
    int ty = tid >> 4, tx = tid & 15;
    int r0 = ty * 4, c0 = tx * 8;
    float acc[4][8];
#pragma unroll
    for (int i = 0; i < 4; i++)
#pragma unroll
        for (int j = 0; j < 8; j++) acc[i][j] = 0.f;
#pragma unroll 4
    for (int k = 0; k < K; k++) {
        float w[8];
        *(float4*)&w[0] = *(float4*)&Ws[k][c0];
        *(float4*)&w[4] = *(float4*)&Ws[k][c0 + 4];
#pragma unroll
        for (int i = 0; i < 4; i++) {
            float xv = xs[r0 + i][k];
#pragma unroll
            for (int j = 0; j < 8; j++) acc[i][j] = fmaf(xv, w[j], acc[i][j]);
        }
    }
    bool is_a = (c0 < 64);
    int cc = is_a ? c0 : (c0 - 64);
#pragma unroll
    for (int i = 0; i < 4; i++) {
        int row = row0 + r0 + i;
        if (row >= NA) continue;
        uint4 hpk = pack_half8(&acc[i][0]);
        if (is_a) {
            *(uint4*)(g_h16_A + (size_t)row * H + cc) = hpk;
            float d = g_dis[OFF_AA + row];
            float dd = d * d;
            float4 o0, o1;
            o0.x = acc[i][0] * dd + bsum[cc + 0];
            o0.y = acc[i][1] * dd + bsum[cc + 1];
            o0.z = acc[i][2] * dd + bsum[cc + 2];
            o0.w = acc[i][3] * dd + bsum[cc + 3];
            o1.x = acc[i][4] * dd + bsum[cc + 4];
            o1.y = acc[i][5] * dd + bsum[cc + 5];
            o1.z = acc[i][6] * dd + bsum[cc + 6];
            o1.w = acc[i][7] * dd + bsum[cc + 7];
            g_acc_a[(size_t)row * (H / 4) + (cc >> 2)]     = o0;
            g_acc_a[(size_t)row * (H / 4) + (cc >> 2) + 1] = o1;
        } else {
            *(uint4*)(g_h16_at + (size_t)row * H + cc) = hpk;
        }
    }
}

// Target transform -> g_h16_A rows [NA, NA+NT)
template <int K, bool RELU>
__global__ __launch_bounds__(256, 3) void transform_target_kernel(
        const float4* __restrict__ x, const float* __restrict__ W) {
    __shared__ float xs[64][K];
    __shared__ float Ws[K][64];
    int tid = threadIdx.x;
    int row0 = blockIdx.x * 64;
    for (int i = tid; i < K * 64; i += 256) {
        int k = i >> 6, c = i & 63;
        Ws[k][c] = W[i];
    }
    constexpr int KV = K / 4;
    for (int i = tid; i < 64 * KV; i += 256) {
        int r = i / KV, kv = i - r * KV;
        int row = row0 + r;
        float4 v = (row < NT) ? x[(size_t)row * KV + kv] : make_float4(0.f, 0.f, 0.f, 0.f);
        if (RELU) { v.x = fmaxf(v.x, 0.f); v.y = fmaxf(v.y, 0.f);
                    v.z = fmaxf(v.z, 0.f); v.w = fmaxf(v.w, 0.f); }
        *(float4*)&xs[r][kv * 4] = v;
    }
    __syncthreads();
    int ty = tid >> 4, tx = tid & 15;
    int r0 = ty * 4, c0 = tx * 4;
    float acc[4][4];
#pragma unroll
    for (int i = 0; i < 4; i++)
#pragma unroll
        for (int j = 0; j < 4; j++) acc[i][j] = 0.f;
#pragma unroll 4
    for (int k = 0; k < K; k++) {
        float w[4];
        *(float4*)&w[0] = *(float4*)&Ws[k][c0];
#pragma unroll
        for (int i = 0; i < 4; i++) {
            float xv = xs[r0 + i][k];
#pragma unroll
            for (int j = 0; j < 4; j++) acc[i][j] = fmaf(xv, w[j], acc[i][j]);
        }
    }
#pragma unroll
    for (int i = 0; i < 4; i++) {
        int row = row0 + r0 + i;
        if (row >= NT) continue;
        __half2 h0 = __floats2half2_rn(acc[i][0], acc[i][1]);
        __half2 h1 = __floats2half2_rn(acc[i][2], acc[i][3]);
        uint2 u; u.x = *(unsigned*)&h0; u.y = *(unsigned*)&h1;
        *(uint2*)(g_h16_A + (size_t)(NA + row) * H + c0) = u;
    }
}

// Gather-based aggregation: warp per dst node, 2 edges in flight (16 lanes each).
__global__ __launch_bounds__(256) void agg_kernel(const float* __restrict__ b_at) {
    int gw = (blockIdx.x * 256 + threadIdx.x) >> 5;
    int lane = threadIdx.x & 31;
    int half = lane >> 4, sub = lane & 15;
    if (gw < NA) {
        int node = gw;
        int beg = g_rs_a[node], end = g_rs_a[node + 1];
        float ax = 0.f, ay = 0.f, az = 0.f, aw = 0.f;
        for (int p = beg + half; p < end; p += 2) {
            int2 ent = __ldg(&g_ent_a[p]);
            float w = __int_as_float(ent.y);
            uint2 raw = *(const uint2*)(g_h16_A + (size_t)ent.x * H + sub * 4);
            float2 f0 = __half22float2(*(__half2*)&raw.x);
            float2 f1 = __half22float2(*(__half2*)&raw.y);
            ax = fmaf(f0.x, w, ax); ay = fmaf(f0.y, w, ay);
            az = fmaf(f1.x, w, az); aw = fmaf(f1.y, w, aw);
        }
        ax += __shfl_down_sync(0xFFFFFFFFu, ax, 16);
        ay += __shfl_down_sync(0xFFFFFFFFu, ay, 16);
        az += __shfl_down_sync(0xFFFFFFFFu, az, 16);
        aw += __shfl_down_sync(0xFFFFFFFFu, aw, 16);
        if (half == 0) {
            float4 base = g_acc_a[(size_t)node * (H / 4) + sub];
            base.x += ax; base.y += ay; base.z += az; base.w += aw;
            g_acc_a[(size_t)node * (H / 4) + sub] = base;
        }
    } else if (gw < NA + NT) {
        int node = gw - NA;
        int beg = g_rs_t[node], end = g_rs_t[node + 1];
        float ax = 0.f, ay = 0.f, az = 0.f, aw = 0.f;
        for (int p = beg + half; p < end; p += 2) {
            int2 ent = __ldg(&g_ent_t[p]);
            float w = __int_as_float(ent.y);
            uint2 raw = *(const uint2*)(g_h16_at + (size_t)ent.x * H + sub * 4);
            float2 f0 = __half22float2(*(__half2*)&raw.x);
            float2 f1 = __half22float2(*(__half2*)&raw.y);
            ax = fmaf(f0.x, w, ax); ay = fmaf(f0.y, w, ay);
            az = fmaf(f1.x, w, az); aw = fmaf(f1.y, w, aw);
        }
        ax += __shfl_down_sync(0xFFFFFFFFu, ax, 16);
        ay += __shfl_down_sync(0xFFFFFFFFu, ay, 16);
        az += __shfl_down_sync(0xFFFFFFFFu, az, 16);
        aw += __shfl_down_sync(0xFFFFFFFFu, aw, 16);
        if (half == 0) {
            int c = sub * 4;
            float4 base = make_float4(b_at[c], b_at[c + 1], b_at[c + 2], b_at[c + 3]);
            base.x += ax; base.y += ay; base.z += az; base.w += aw;
            g_acc_t[(size_t)node * (H / 4) + sub] = base;
        }
    }
}

// One warp per row: out[row,:] = g[row,:] @ Wp + bp
__global__ void proj_kernel(const float* __restrict__ g,
                            const float* __restrict__ Wp,
                            const float* __restrict__ bp,
                            float* __restrict__ out, int n) {
    int idx = blockIdx.x * blockDim.x + threadIdx.x;
    int row = idx >> 5, lane = idx & 31;
    if (row >= n) return;
    float g0 = g[(size_t)row * H + lane];
    float g1 = g[(size_t)row * H + lane + 32];
    float p0 = g0 * Wp[lane * 2 + 0] + g1 * Wp[(lane + 32) * 2 + 0];
    float p1 = g0 * Wp[lane * 2 + 1] + g1 * Wp[(lane + 32) * 2 + 1];
#pragma unroll
    for (int o = 16; o; o >>= 1) {
        p0 += __shfl_down_sync(0xFFFFFFFFu, p0, o);
        p1 += __shfl_down_sync(0xFFFFFFFFu, p1, o);
    }
    if (lane == 0) {
        out[(size_t)row * 2 + 0] = p0 + bp[0];
        out[(size_t)row * 2 + 1] = p1 + bp[1];
    }
}

// ---------------------------------------------------------------------------
static inline int cdiv(long long a, int b) { return (int)((a + b - 1) / b); }

extern "C" void kernel_launch(void* const* d_in, const int* in_sizes, int n_in,
                              void* d_out, int out_size) {
    const float* x_agent  = (const float*)d_in[1];
    const float* x_target = (const float*)d_in[2];
    const int* src_aa = (const int*)d_in[3];
    const int* dst_aa = (const int*)d_in[4];
    const int* src_at = (const int*)d_in[5];
    const int* dst_at = (const int*)d_in[6];
    const int* src_ta = (const int*)d_in[7];
    const int* dst_ta = (const int*)d_in[8];
    const float* W1_aa = (const float*)d_in[9];
    const float* b1_aa = (const float*)d_in[10];
    const float* W1_at = (const float*)d_in[11];
    const float* b1_at = (const float*)d_in[12];
    const float* W1_ta = (const float*)d_in[13];
    const float* b1_ta = (const float*)d_in[14];
    const float* W2_aa = (const float*)d_in[15];
    const float* b2_aa = (const float*)d_in[16];
    const float* W2_at = (const float*)d_in[17];
    const float* b2_at = (const float*)d_in[18];
    const float* W2_ta = (const float*)d_in[19];
    const float* b2_ta = (const float*)d_in[20];
    const float* Wp_agent  = (const float*)d_in[21];
    const float* bp_agent  = (const float*)d_in[22];
    const float* Wp_target = (const float*)d_in[23];
    const float* bp_target = (const float*)d_in[24];
    float* out = (float*)d_out;

    void *p_acca, *p_acct;
    cudaGetSymbolAddress(&p_acca, g_acc_a);
    cudaGetSymbolAddress(&p_acct, g_acc_t);
    float* acc_a = (float*)p_acca;
    float* acc_t = (float*)p_acct;

    // ---- degrees / norms / CSR (once; reused by both layers) ----
    zero_cnt_kernel<<<cdiv(NTOT, 256), 256>>>();
    constexpr long long CNT_TOT = E_AA + 2LL * E_AT + 2LL * E_TA;
    count_all_kernel<<<cdiv(CNT_TOT, 256), 256>>>(dst_aa, src_at, dst_at, src_ta, dst_ta);
    dis_kernel<<<cdiv(NTOT, 256), 256>>>();
    scan_local_kernel<<<NBLK, 1024>>>();
    scan_mid_kernel<<<1, 128>>>();
    scan_add_kernel<<<NBLK, 1024>>>();
    constexpr long long E_TOT = E_AA + E_TA + E_AT;
    fill_kernel<<<cdiv(E_TOT, 256), 256>>>(src_aa, dst_aa, src_ta, dst_ta, src_at, dst_at);

    constexpr long long AGG_THREADS = (long long)(NA + NT) * 32;

    // ---- layer 1 ----
    transform_agent_kernel<DIN, false><<<cdiv(NA, 64), 256>>>(
        (const float4*)x_agent, W1_aa, W1_at, b1_aa, b1_ta);
    transform_target_kernel<DIN, false><<<cdiv(NT, 64), 256>>>(
        (const float4*)x_target, W1_ta);
    agg_kernel<<<cdiv(AGG_THREADS, 256), 256>>>(b1_at);

    // ---- layer 2 ----
    transform_agent_kernel<H, true><<<cdiv(NA, 64), 256>>>(
        (const float4*)acc_a, W2_aa, W2_at, b2_aa, b2_ta);
    transform_target_kernel<H, true><<<cdiv(NT, 64), 256>>>(
        (const float4*)acc_t, W2_ta);
    agg_kernel<<<cdiv(AGG_THREADS, 256), 256>>>(b2_at);

    // ---- output projections ----
    proj_kernel<<<cdiv((long long)NA * 32, 256), 256>>>(acc_a, Wp_agent,  bp_agent,  out, NA);
    proj_kernel<<<cdiv((long long)NT * 32, 256), 256>>>(acc_t, Wp_target, bp_target, out + (size_t)NA * 2, NT);
}

// round 7
// speedup vs baseline: 1.6400x; 1.0251x over previous
#include <cuda_runtime.h>
#include <cuda_fp16.h>
#include <math.h>

constexpr int NA = 50000;
constexpr int NT = 25000;
constexpr int DIN = 32;
constexpr int H = 64;
constexpr int E_AA = 800000;
constexpr int E_AT = 400000;
constexpr int E_TA = 400000;

constexpr int OFF_AA   = 0;
constexpr int OFF_AT_S = NA;
constexpr int OFF_TA_D = 2 * NA;
constexpr int OFF_AT_D = 3 * NA;
constexpr int OFF_TA_S = 3 * NA + NT;
constexpr int NTOT = 3 * NA + 2 * NT;

constexpr int NBLK_A = (NA + 1023) / 1024;   // 49
constexpr int NBLK_T = (NT + 1023) / 1024;   // 25
constexpr int NBLK   = NBLK_A + NBLK_T;      // 74

// scratch
__device__ int    g_cnt[NTOT];
__device__ float  g_dis[NTOT];
__device__ __half g_h16_A[(size_t)(NA + NT) * H];   // rows [0,NA)=h_aa, [NA,NA+NT)=h_ta
__device__ __half g_h16_at[(size_t)NA * H];         // agent->target features
__device__ float4 g_acc_a[(size_t)NA * H / 4];
__device__ float4 g_acc_t[(size_t)NT * H / 4];
// CSR (built once per launch; valid for both layers)
__device__ int  g_rs_a[NA + 1];
__device__ int  g_rs_t[NT + 1];
__device__ int  g_cur_a[NA];
__device__ int  g_cur_t[NT];
__device__ int2 g_ent_a[E_AA + E_TA];               // {src_idx into g_h16_A, w as bits}
__device__ int2 g_ent_t[E_AT];                      // {src agent, w as bits}
__device__ int  g_part[NBLK];
__device__ int  g_partscan[NBLK];

// ---------------------------------------------------------------------------
__global__ void zero_cnt_kernel() {
    int i = blockIdx.x * blockDim.x + threadIdx.x;
    if (i < NTOT) g_cnt[i] = 0;
}

// 4 edges/thread via int4 loads; all five degree histograms in one launch.
__global__ void count_all_kernel(const int* __restrict__ dst_aa,
                                 const int* __restrict__ src_at,
                                 const int* __restrict__ dst_at,
                                 const int* __restrict__ src_ta,
                                 const int* __restrict__ dst_ta) {
    constexpr int G_AA = E_AA / 4, G_AT = E_AT / 4, G_TA = E_TA / 4;
    int i = blockIdx.x * blockDim.x + threadIdx.x;
    const int* p; int off, j;
    if (i < G_AA)                           { p = dst_aa; off = OFF_AA;   j = i; }
    else if (i < G_AA + G_AT)               { p = src_at; off = OFF_AT_S; j = i - G_AA; }
    else if (i < G_AA + 2 * G_AT)           { p = dst_at; off = OFF_AT_D; j = i - G_AA - G_AT; }
    else if (i < G_AA + 2 * G_AT + G_TA)    { p = src_ta; off = OFF_TA_S; j = i - G_AA - 2 * G_AT; }
    else if (i < G_AA + 2 * G_AT + 2*G_TA)  { p = dst_ta; off = OFF_TA_D; j = i - G_AA - 2 * G_AT - G_TA; }
    else return;
    int4 v = *(const int4*)(p + j * 4);
    atomicAdd(&g_cnt[off + v.x], 1);
    atomicAdd(&g_cnt[off + v.y], 1);
    atomicAdd(&g_cnt[off + v.z], 1);
    atomicAdd(&g_cnt[off + v.w], 1);
}

__global__ void dis_kernel() {
    int i = blockIdx.x * blockDim.x + threadIdx.x;
    if (i >= NTOT) return;
    int c = g_cnt[i];
    float d;
    if (i < NA) d = rsqrtf((float)c + 1.0f);
    else        d = (c > 0) ? rsqrtf((float)c) : 0.0f;
    g_dis[i] = d;
}

// Phase 1: per-block local exclusive scan (1024 elems/block) + block partial.
__global__ __launch_bounds__(1024) void scan_local_kernel() {
    __shared__ int sm[1024];
    int b = blockIdx.x;
    bool isA = (b < NBLK_A);
    int base = isA ? b * 1024 : (b - NBLK_A) * 1024;
    int n = isA ? NA : NT;
    int tid = threadIdx.x;
    int i = base + tid;
    int v = 0;
    if (i < n) {
        if (isA) { v = g_cnt[OFF_AA + i] + g_cnt[OFF_TA_D + i]; g_cur_a[i] = 0; }
        else     { v = g_cnt[OFF_AT_D + i];                     g_cur_t[i] = 0; }
    }
    sm[tid] = v;
    __syncthreads();
#pragma unroll
    for (int off = 1; off < 1024; off <<= 1) {
        int u = (tid >= off) ? sm[tid - off] : 0;
        __syncthreads();
        sm[tid] += u;
        __syncthreads();
    }
    if (i < n) {
        int excl = sm[tid] - v;
        if (isA) g_rs_a[i] = excl; else g_rs_t[i] = excl;
    }
    if (tid == 1023) g_part[b] = sm[1023];
}

// Phase 2: segmented scan of the 74 block partials.
__global__ void scan_mid_kernel() {
    __shared__ int sp[NBLK];
    __shared__ int so[NBLK + 2];
    int tid = threadIdx.x;
    if (tid < NBLK) sp[tid] = g_part[tid];
    __syncthreads();
    if (tid == 0) {
        int s = 0;
        for (int b = 0; b < NBLK_A; b++) { so[b] = s; s += sp[b]; }
        so[NBLK] = s;
        s = 0;
        for (int b = NBLK_A; b < NBLK; b++) { so[b] = s; s += sp[b]; }
        so[NBLK + 1] = s;
    }
    __syncthreads();
    if (tid < NBLK) g_partscan[tid] = so[tid];
    if (tid == 0) { g_rs_a[NA] = so[NBLK]; g_rs_t[NT] = so[NBLK + 1]; }
}

// Phase 3: add block offsets.
__global__ __launch_bounds__(1024) void scan_add_kernel() {
    int b = blockIdx.x;
    if (b == 0) return;
    bool isA = (b < NBLK_A);
    if (!isA && b == NBLK_A) return;
    int base = isA ? b * 1024 : (b - NBLK_A) * 1024;
    int n = isA ? NA : NT;
    int i = base + threadIdx.x;
    int off = g_partscan[b];
    if (i < n) { if (isA) g_rs_a[i] += off; else g_rs_t[i] += off; }
}

// Place every edge into its dst segment.
__global__ void fill_kernel(const int* __restrict__ src_aa, const int* __restrict__ dst_aa,
                            const int* __restrict__ src_ta, const int* __restrict__ dst_ta,
                            const int* __restrict__ src_at, const int* __restrict__ dst_at) {
    int i = blockIdx.x * blockDim.x + threadIdx.x;
    if (i < E_AA) {
        int s = src_aa[i], d = dst_aa[i];
        float w = g_dis[OFF_AA + s] * g_dis[OFF_AA + d];
        int pos = g_rs_a[d] + atomicAdd(&g_cur_a[d], 1);
        g_ent_a[pos] = make_int2(s, __float_as_int(w));
    } else if (i < E_AA + E_TA) {
        int j = i - E_AA;
        int s = src_ta[j], d = dst_ta[j];
        float w = g_dis[OFF_TA_S + s] * g_dis[OFF_TA_D + d];
        int pos = g_rs_a[d] + atomicAdd(&g_cur_a[d], 1);
        g_ent_a[pos] = make_int2(NA + s, __float_as_int(w));
    } else if (i < E_AA + E_TA + E_AT) {
        int j = i - E_AA - E_TA;
        int s = src_at[j], d = dst_at[j];
        float w = g_dis[OFF_AT_S + s] * g_dis[OFF_AT_D + d];
        int pos = g_rs_t[d] + atomicAdd(&g_cur_t[d], 1);
        g_ent_t[pos] = make_int2(s, __float_as_int(w));
    }
}

// Agent transform, fused epilogue. 512 threads, BM=64, 128 cols, TM=4, TN=4.
template <int K, bool RELU>
__global__ __launch_bounds__(512, 2) void transform_agent_kernel(
        const float4* __restrict__ x,
        const float* __restrict__ Wa, const float* __restrict__ Wb,
        const float* __restrict__ b_aa, const float* __restrict__ b_ta) {
    __shared__ float xs[64][K];
    __shared__ float Ws[K][128];
    __shared__ float bsum[64];
    int tid = threadIdx.x;
    int row0 = blockIdx.x * 64;
    for (int i = tid; i < K * 64; i += 512) {
        int k = i >> 6, c = i & 63;
        Ws[k][c]      = Wa[i];
        Ws[k][c + 64] = Wb[i];
    }
    if (tid < 64) bsum[tid] = b_aa[tid] + b_ta[tid];
    constexpr int KV = K / 4;
    for (int i = tid; i < 64 * KV; i += 512) {
        int r = i / KV, kv = i - r * KV;
        int row = row0 + r;
        float4 v = (row < NA) ? x[(size_t)row * KV + kv] : make_float4(0.f, 0.f, 0.f, 0.f);
        if (RELU) { v.x = fmaxf(v.x, 0.f); v.y = fmaxf(v.y, 0.f);
                    v.z = fmaxf(v.z, 0.f); v.w = fmaxf(v.w, 0.f); }
        *(float4*)&xs[r][kv * 4] = v;
    }
    __syncthreads();
    int ty = tid >> 5, tx = tid & 31;    // 16 row groups x 32 col groups
    int r0 = ty * 4, c0 = tx * 4;
    float acc[4][4];
#pragma unroll
    for (int i = 0; i < 4; i++)
#pragma unroll
        for (int j = 0; j < 4; j++) acc[i][j] = 0.f;
#pragma unroll 4
    for (int k = 0; k < K; k++) {
        float w[4];
        *(float4*)&w[0] = *(float4*)&Ws[k][c0];
#pragma unroll
        for (int i = 0; i < 4; i++) {
            float xv = xs[r0 + i][k];
#pragma unroll
            for (int j = 0; j < 4; j++) acc[i][j] = fmaf(xv, w[j], acc[i][j]);
        }
    }
    bool is_a = (c0 < 64);
    int cc = is_a ? c0 : (c0 - 64);
#pragma unroll
    for (int i = 0; i < 4; i++) {
        int row = row0 + r0 + i;
        if (row >= NA) continue;
        __half2 h0 = __floats2half2_rn(acc[i][0], acc[i][1]);
        __half2 h1 = __floats2half2_rn(acc[i][2], acc[i][3]);
        uint2 hpk; hpk.x = *(unsigned*)&h0; hpk.y = *(unsigned*)&h1;
        if (is_a) {
            *(uint2*)(g_h16_A + (size_t)row * H + cc) = hpk;
            float d = g_dis[OFF_AA + row];
            float dd = d * d;
            float4 o;
            o.x = acc[i][0] * dd + bsum[cc + 0];
            o.y = acc[i][1] * dd + bsum[cc + 1];
            o.z = acc[i][2] * dd + bsum[cc + 2];
            o.w = acc[i][3] * dd + bsum[cc + 3];
            g_acc_a[(size_t)row * (H / 4) + (cc >> 2)] = o;
        } else {
            *(uint2*)(g_h16_at + (size_t)row * H + cc) = hpk;
        }
    }
}

// Target transform -> g_h16_A rows [NA, NA+NT). 256 threads, BM=64, TM=4, TN=4.
template <int K, bool RELU>
__global__ __launch_bounds__(256, 3) void transform_target_kernel(
        const float4* __restrict__ x, const float* __restrict__ W) {
    __shared__ float xs[64][K];
    __shared__ float Ws[K][64];
    int tid = threadIdx.x;
    int row0 = blockIdx.x * 64;
    for (int i = tid; i < K * 64; i += 256) {
        int k = i >> 6, c = i & 63;
        Ws[k][c] = W[i];
    }
    constexpr int KV = K / 4;
    for (int i = tid; i < 64 * KV; i += 256) {
        int r = i / KV, kv = i - r * KV;
        int row = row0 + r;
        float4 v = (row < NT) ? x[(size_t)row * KV + kv] : make_float4(0.f, 0.f, 0.f, 0.f);
        if (RELU) { v.x = fmaxf(v.x, 0.f); v.y = fmaxf(v.y, 0.f);
                    v.z = fmaxf(v.z, 0.f); v.w = fmaxf(v.w, 0.f); }
        *(float4*)&xs[r][kv * 4] = v;
    }
    __syncthreads();
    int ty = tid >> 4, tx = tid & 15;
    int r0 = ty * 4, c0 = tx * 4;
    float acc[4][4];
#pragma unroll
    for (int i = 0; i < 4; i++)
#pragma unroll
        for (int j = 0; j < 4; j++) acc[i][j] = 0.f;
#pragma unroll 4
    for (int k = 0; k < K; k++) {
        float w[4];
        *(float4*)&w[0] = *(float4*)&Ws[k][c0];
#pragma unroll
        for (int i = 0; i < 4; i++) {
            float xv = xs[r0 + i][k];
#pragma unroll
            for (int j = 0; j < 4; j++) acc[i][j] = fmaf(xv, w[j], acc[i][j]);
        }
    }
#pragma unroll
    for (int i = 0; i < 4; i++) {
        int row = row0 + r0 + i;
        if (row >= NT) continue;
        __half2 h0 = __floats2half2_rn(acc[i][0], acc[i][1]);
        __half2 h1 = __floats2half2_rn(acc[i][2], acc[i][3]);
        uint2 u; u.x = *(unsigned*)&h0; u.y = *(unsigned*)&h1;
        *(uint2*)(g_h16_A + (size_t)(NA + row) * H + c0) = u;
    }
}

// Gather aggregation: warp per dst node, 4 edges in flight (8 lanes/edge, 16B gathers).
__global__ __launch_bounds__(256) void agg_kernel(const float* __restrict__ b_at) {
    int gw = (blockIdx.x * 256 + threadIdx.x) >> 5;
    int lane = threadIdx.x & 31;
    int grp = lane >> 3, sub = lane & 7;
    float a[8];
#pragma unroll
    for (int j = 0; j < 8; j++) a[j] = 0.f;
    if (gw < NA) {
        int beg = g_rs_a[gw], end = g_rs_a[gw + 1];
        for (int p = beg + grp; p < end; p += 4) {
            int2 ent = __ldg(&g_ent_a[p]);
            float w = __int_as_float(ent.y);
            uint4 raw = *(const uint4*)(g_h16_A + (size_t)ent.x * H + sub * 8);
            float2 f0 = __half22float2(*(__half2*)&raw.x);
            float2 f1 = __half22float2(*(__half2*)&raw.y);
            float2 f2 = __half22float2(*(__half2*)&raw.z);
            float2 f3 = __half22float2(*(__half2*)&raw.w);
            a[0] = fmaf(f0.x, w, a[0]); a[1] = fmaf(f0.y, w, a[1]);
            a[2] = fmaf(f1.x, w, a[2]); a[3] = fmaf(f1.y, w, a[3]);
            a[4] = fmaf(f2.x, w, a[4]); a[5] = fmaf(f2.y, w, a[5]);
            a[6] = fmaf(f3.x, w, a[6]); a[7] = fmaf(f3.y, w, a[7]);
        }
#pragma unroll
        for (int j = 0; j < 8; j++) {
            a[j] += __shfl_down_sync(0xFFFFFFFFu, a[j], 16);
            a[j] += __shfl_down_sync(0xFFFFFFFFu, a[j], 8);
        }
        if (grp == 0) {
            size_t base = (size_t)gw * (H / 4) + sub * 2;
            float4 b0 = g_acc_a[base], b1 = g_acc_a[base + 1];
            b0.x += a[0]; b0.y += a[1]; b0.z += a[2]; b0.w += a[3];
            b1.x += a[4]; b1.y += a[5]; b1.z += a[6]; b1.w += a[7];
            g_acc_a[base] = b0; g_acc_a[base + 1] = b1;
        }
    } else if (gw < NA + NT) {
        int node = gw - NA;
        int beg = g_rs_t[node], end = g_rs_t[node + 1];
        for (int p = beg + grp; p < end; p += 4) {
            int2 ent = __ldg(&g_ent_t[p]);
            float w = __int_as_float(ent.y);
            uint4 raw = *(const uint4*)(g_h16_at + (size_t)ent.x * H + sub * 8);
            float2 f0 = __half22float2(*(__half2*)&raw.x);
            float2 f1 = __half22float2(*(__half2*)&raw.y);
            float2 f2 = __half22float2(*(__half2*)&raw.z);
            float2 f3 = __half22float2(*(__half2*)&raw.w);
            a[0] = fmaf(f0.x, w, a[0]); a[1] = fmaf(f0.y, w, a[1]);
            a[2] = fmaf(f1.x, w, a[2]); a[3] = fmaf(f1.y, w, a[3]);
            a[4] = fmaf(f2.x, w, a[4]); a[5] = fmaf(f2.y, w, a[5]);
            a[6] = fmaf(f3.x, w, a[6]); a[7] = fmaf(f3.y, w, a[7]);
        }
#pragma unroll
        for (int j = 0; j < 8; j++) {
            a[j] += __shfl_down_sync(0xFFFFFFFFu, a[j], 16);
            a[j] += __shfl_down_sync(0xFFFFFFFFu, a[j], 8);
        }
        if (grp == 0) {
            int c = sub * 8;
            float4 b0 = make_float4(b_at[c],     b_at[c + 1], b_at[c + 2], b_at[c + 3]);
            float4 b1 = make_float4(b_at[c + 4], b_at[c + 5], b_at[c + 6], b_at[c + 7]);
            b0.x += a[0]; b0.y += a[1]; b0.z += a[2]; b0.w += a[3];
            b1.x += a[4]; b1.y += a[5]; b1.z += a[6]; b1.w += a[7];
            size_t base = (size_t)node * (H / 4) + sub * 2;
            g_acc_t[base] = b0; g_acc_t[base + 1] = b1;
        }
    }
}

// One warp per row; handles both node types in one launch.
__global__ void proj_kernel(const float* __restrict__ Wp_a, const float* __restrict__ bp_a,
                            const float* __restrict__ Wp_t, const float* __restrict__ bp_t,
                            float* __restrict__ out) {
    int idx = blockIdx.x * blockDim.x + threadIdx.x;
    int row = idx >> 5, lane = idx & 31;
    if (row >= NA + NT) return;
    const float* g; const float* Wp; const float* bp; float* o;
    if (row < NA) {
        g = (const float*)g_acc_a + (size_t)row * H;
        Wp = Wp_a; bp = bp_a; o = out + (size_t)row * 2;
    } else {
        g = (const float*)g_acc_t + (size_t)(row - NA) * H;
        Wp = Wp_t; bp = bp_t; o = out + (size_t)row * 2;
    }
    float g0 = g[lane];
    float g1 = g[lane + 32];
    float p0 = g0 * Wp[lane * 2 + 0] + g1 * Wp[(lane + 32) * 2 + 0];
    float p1 = g0 * Wp[lane * 2 + 1] + g1 * Wp[(lane + 32) * 2 + 1];
#pragma unroll
    for (int off = 16; off; off >>= 1) {
        p0 += __shfl_down_sync(0xFFFFFFFFu, p0, off);
        p1 += __shfl_down_sync(0xFFFFFFFFu, p1, off);
    }
    if (lane == 0) { o[0] = p0 + bp[0]; o[1] = p1 + bp[1]; }
}

// ---------------------------------------------------------------------------
static inline int cdiv(long long a, int b) { return (int)((a + b - 1) / b); }

extern "C" void kernel_launch(void* const* d_in, const int* in_sizes, int n_in,
                              void* d_out, int out_size) {
    const float* x_agent  = (const float*)d_in[1];
    const float* x_target = (const float*)d_in[2];
    const int* src_aa = (const int*)d_in[3];
    const int* dst_aa = (const int*)d_in[4];
    const int* src_at = (const int*)d_in[5];
    const int* dst_at = (const int*)d_in[6];
    const int* src_ta = (const int*)d_in[7];
    const int* dst_ta = (const int*)d_in[8];
    const float* W1_aa = (const float*)d_in[9];
    const float* b1_aa = (const float*)d_in[10];
    const float* W1_at = (const float*)d_in[11];
    const float* b1_at = (const float*)d_in[12];
    const float* W1_ta = (const float*)d_in[13];
    const float* b1_ta = (const float*)d_in[14];
    const float* W2_aa = (const float*)d_in[15];
    const float* b2_aa = (const float*)d_in[16];
    const float* W2_at = (const float*)d_in[17];
    const float* b2_at = (const float*)d_in[18];
    const float* W2_ta = (const float*)d_in[19];
    const float* b2_ta = (const float*)d_in[20];
    const float* Wp_agent  = (const float*)d_in[21];
    const float* bp_agent  = (const float*)d_in[22];
    const float* Wp_target = (const float*)d_in[23];
    const float* bp_target = (const float*)d_in[24];
    float* out = (float*)d_out;

    void *p_acca, *p_acct;
    cudaGetSymbolAddress(&p_acca, g_acc_a);
    cudaGetSymbolAddress(&p_acct, g_acc_t);
    float* acc_a = (float*)p_acca;
    float* acc_t = (float*)p_acct;

    // ---- degrees / norms / CSR (once; reused by both layers) ----
    zero_cnt_kernel<<<cdiv(NTOT, 256), 256>>>();
    constexpr long long CNT_G = (E_AA + 2LL * E_AT + 2LL * E_TA) / 4;
    count_all_kernel<<<cdiv(CNT_G, 256), 256>>>(dst_aa, src_at, dst_at, src_ta, dst_ta);
    dis_kernel<<<cdiv(NTOT, 256), 256>>>();
    scan_local_kernel<<<NBLK, 1024>>>();
    scan_mid_kernel<<<1, 128>>>();
    scan_add_kernel<<<NBLK, 1024>>>();
    constexpr long long E_TOT = E_AA + E_TA + E_AT;
    fill_kernel<<<cdiv(E_TOT, 256), 256>>>(src_aa, dst_aa, src_ta, dst_ta, src_at, dst_at);

    constexpr long long AGG_THREADS = (long long)(NA + NT) * 32;

    // ---- layer 1 ----
    transform_agent_kernel<DIN, false><<<cdiv(NA, 64), 512>>>(
        (const float4*)x_agent, W1_aa, W1_at, b1_aa, b1_ta);
    transform_target_kernel<DIN, false><<<cdiv(NT, 64), 256>>>(
        (const float4*)x_target, W1_ta);
    agg_kernel<<<cdiv(AGG_THREADS, 256), 256>>>(b1_at);

    // ---- layer 2 ----
    transform_agent_kernel<H, true><<<cdiv(NA, 64), 512>>>(
        (const float4*)acc_a, W2_aa, W2_at, b2_aa, b2_ta);
    transform_target_kernel<H, true><<<cdiv(NT, 64), 256>>>(
        (const float4*)acc_t, W2_ta);
    agg_kernel<<<cdiv(AGG_THREADS, 256), 256>>>(b2_at);

    // ---- output projection (both types, one launch) ----
    proj_kernel<<<cdiv((long long)(NA + NT) * 32, 256), 256>>>(
        Wp_agent, bp_agent, Wp_target, bp_target, out);
}